// round 2
// baseline (speedup 1.0000x reference)
#include <cuda_runtime.h>
#include <cstdint>
#include <cstdio>

// ---------------- problem constants ----------------
#define Hdim   256
#define GD     16
#define GL     16
#define NLAY   2
#define NH     4
#define DH     64          // Hdim / NH
#define CS     256
#define TOTAL  263168      // == NCH * CS exactly
#define NCH    1028
#define BATCH  16

// ---------------- intermediate buffers (no allocation allowed) ----------------
__device__ float g_h[BATCH * GL * Hdim];        // 65536
__device__ float g_qkv[BATCH * GL * 3 * Hdim];  // 196608
__device__ float g_attn[BATCH * GL * Hdim];     // 65536
__device__ float g_tmp[BATCH * GL * Hdim];      // 65536
__device__ float g_ffn[BATCH * GL * 4 * Hdim];  // 262144
__device__ float g_latent[BATCH * Hdim];        // 4096

// =====================================================================
// Transformer preamble kernels (fp32, simple but parallel enough)
// =====================================================================

__global__ void embed_kernel(const float* __restrict__ g,
                             const float* __restrict__ W,
                             const float* __restrict__ bias,
                             float* __restrict__ h)
{
    int row = blockIdx.x;          // b*GL + s   (256 rows)
    int j   = threadIdx.x;         // 256
    __shared__ float sg[GD];
    if (j < GD) sg[j] = g[row * GD + j];
    __syncthreads();
    float a = bias[j];
    const float* w = W + j * GD;
#pragma unroll
    for (int d = 0; d < GD; d++) a = fmaf(sg[d], w[d], a);
    h[row * Hdim + j] = a;
}

// generic: block computes 4 input rows x NOUT outputs; W is [NOUT, KD] row-major
template<int NOUT, int KD, bool RELU>
__global__ void gemm_rows4(const float* __restrict__ X,
                           const float* __restrict__ W,
                           const float* __restrict__ bias,
                           float* __restrict__ Y)
{
    __shared__ float sx[4 * KD];
    int j  = threadIdx.x;          // NOUT threads
    int r0 = blockIdx.x * 4;
    for (int i = j; i < 4 * KD; i += NOUT) sx[i] = X[r0 * KD + i];
    __syncthreads();
    float bv = bias[j];
    float a0 = bv, a1 = bv, a2 = bv, a3 = bv;
    const float* w = W + (size_t)j * KD;
#pragma unroll 4
    for (int k = 0; k < KD; k += 4) {
        float4 wv = *reinterpret_cast<const float4*>(w + k);
        a0 = fmaf(sx[0*KD + k    ], wv.x, a0);
        a0 = fmaf(sx[0*KD + k + 1], wv.y, a0);
        a0 = fmaf(sx[0*KD + k + 2], wv.z, a0);
        a0 = fmaf(sx[0*KD + k + 3], wv.w, a0);
        a1 = fmaf(sx[1*KD + k    ], wv.x, a1);
        a1 = fmaf(sx[1*KD + k + 1], wv.y, a1);
        a1 = fmaf(sx[1*KD + k + 2], wv.z, a1);
        a1 = fmaf(sx[1*KD + k + 3], wv.w, a1);
        a2 = fmaf(sx[2*KD + k    ], wv.x, a2);
        a2 = fmaf(sx[2*KD + k + 1], wv.y, a2);
        a2 = fmaf(sx[2*KD + k + 2], wv.z, a2);
        a2 = fmaf(sx[2*KD + k + 3], wv.w, a2);
        a3 = fmaf(sx[3*KD + k    ], wv.x, a3);
        a3 = fmaf(sx[3*KD + k + 1], wv.y, a3);
        a3 = fmaf(sx[3*KD + k + 2], wv.z, a3);
        a3 = fmaf(sx[3*KD + k + 3], wv.w, a3);
    }
    if (RELU) {
        a0 = fmaxf(a0, 0.f); a1 = fmaxf(a1, 0.f);
        a2 = fmaxf(a2, 0.f); a3 = fmaxf(a3, 0.f);
    }
    Y[(size_t)(r0 + 0) * NOUT + j] = a0;
    Y[(size_t)(r0 + 1) * NOUT + j] = a1;
    Y[(size_t)(r0 + 2) * NOUT + j] = a2;
    Y[(size_t)(r0 + 3) * NOUT + j] = a3;
}

// attention for one (b, head): 64 blocks, 256 threads
__global__ void attn_kernel(const float* __restrict__ qkv,
                            float* __restrict__ obuf)
{
    int b    = blockIdx.x >> 2;
    int head = blockIdx.x & 3;
    __shared__ float sq[GL][DH], sk[GL][DH], sv[GL][DH], sa[GL][GL];
    int tid = threadIdx.x;
    for (int i = tid; i < GL * DH; i += 256) {
        int s_ = i >> 6, d = i & 63;
        int base = (b * GL + s_) * (3 * Hdim) + head * DH + d;
        sq[s_][d] = qkv[base];
        sk[s_][d] = qkv[base + Hdim];
        sv[s_][d] = qkv[base + 2 * Hdim];
    }
    __syncthreads();
    int s_ = tid >> 4, t_ = tid & 15;
    float sc = 0.f;
#pragma unroll
    for (int d = 0; d < DH; d++) sc = fmaf(sq[s_][d], sk[t_][d], sc);
    sc *= 0.125f;  // 1/sqrt(64)
    // softmax over t_ within aligned 16-lane segment
    float mx = sc;
#pragma unroll
    for (int m = 8; m > 0; m >>= 1) mx = fmaxf(mx, __shfl_xor_sync(0xffffffffu, mx, m));
    float e = __expf(sc - mx);
    float sum = e;
#pragma unroll
    for (int m = 8; m > 0; m >>= 1) sum += __shfl_xor_sync(0xffffffffu, sum, m);
    sa[s_][t_] = e / sum;
    __syncthreads();
    int d4 = tid & 15; s_ = tid >> 4;
#pragma unroll
    for (int dd = 0; dd < 4; dd++) {
        int d = d4 * 4 + dd;
        float acc = 0.f;
#pragma unroll
        for (int t = 0; t < GL; t++) acc = fmaf(sa[s_][t], sv[t][d], acc);
        obuf[(b * GL + s_) * Hdim + head * DH + d] = acc;
    }
}

// residual add + LayerNorm (in-place update of h)
__global__ void addln_kernel(const float* __restrict__ y,
                             float* __restrict__ h,
                             const float* __restrict__ gamma,
                             const float* __restrict__ beta)
{
    int row = blockIdx.x;      // 256 rows
    int j   = threadIdx.x;     // 256
    __shared__ float red[16];
    float v = y[row * Hdim + j] + h[row * Hdim + j];
    float s1 = v, s2 = v * v;
#pragma unroll
    for (int m = 16; m > 0; m >>= 1) {
        s1 += __shfl_xor_sync(0xffffffffu, s1, m);
        s2 += __shfl_xor_sync(0xffffffffu, s2, m);
    }
    int w = j >> 5;
    if ((j & 31) == 0) { red[w] = s1; red[8 + w] = s2; }
    __syncthreads();
    float S1 = 0.f, S2 = 0.f;
#pragma unroll
    for (int i = 0; i < 8; i++) { S1 += red[i]; S2 += red[8 + i]; }
    float mean = S1 * (1.f / 256.f);
    float var  = S2 * (1.f / 256.f) - mean * mean;
    h[row * Hdim + j] = (v - mean) * rsqrtf(var + 1e-5f) * gamma[j] + beta[j];
}

__global__ void latent_kernel(const float* __restrict__ h,
                              float* __restrict__ lat)
{
    int b = blockIdx.x, j = threadIdx.x;
    float a = 0.f;
#pragma unroll
    for (int s = 0; s < GL; s++) a += h[(b * GL + s) * Hdim + j];
    lat[b * Hdim + j] = a * (1.f / 16.f);
}

// =====================================================================
// GRU scan: 16 clusters (one per batch) x 8 CTAs, weights register-resident
// =====================================================================

#define GRU_CLUSTER 8
// smem padding: +4 floats per 32 -> 8 lane-slices hit disjoint bank quads
__device__ __forceinline__ int SPAD(int i) { return i + ((i >> 5) << 2); }

__device__ __forceinline__ void cluster_sync_()
{
    asm volatile("barrier.cluster.arrive.aligned;" ::: "memory");
    asm volatile("barrier.cluster.wait.aligned;"   ::: "memory");
}

__device__ __forceinline__ void st_remote(float* p, int rank, float v)
{
    uint32_t a = (uint32_t)__cvta_generic_to_shared(p);
    uint32_t ra;
    asm volatile("mapa.shared::cluster.u32 %0, %1, %2;" : "=r"(ra) : "r"(a), "r"(rank));
    asm volatile("st.shared::cluster.f32 [%0], %1;" :: "r"(ra), "f"(v) : "memory");
}

#define FMA4(acc, warr, i4)                                \
    acc = fmaf(xv.x, warr[4*(i4)+0], acc);                 \
    acc = fmaf(xv.y, warr[4*(i4)+1], acc);                 \
    acc = fmaf(xv.z, warr[4*(i4)+2], acc);                 \
    acc = fmaf(xv.w, warr[4*(i4)+3], acc);

__global__ void __cluster_dims__(GRU_CLUSTER, 1, 1) __launch_bounds__(256, 1)
gru_kernel(const float* __restrict__ Wih, const float* __restrict__ Whh,
           const float* __restrict__ bih, const float* __restrict__ bhh,
           const float* __restrict__ Wo,  const float* __restrict__ ob,
           const float* __restrict__ latent, float* __restrict__ out)
{
    __shared__ __align__(16) float sx[296];
    __shared__ __align__(16) float sh[296];

    unsigned r;
    asm("mov.u32 %0, %%cluster_ctarank;" : "=r"(r));
    int b  = blockIdx.x >> 3;
    int t  = threadIdx.x;
    int G  = t >> 3;            // reduction group 0..31
    int s  = t & 7;             // k-slice / target rank
    int j  = (int)r * 32 + G;   // owned hid index == owned out row
    int k0 = s * 32;

    // ---- register-resident weight slices: 7 x 32 = 224 floats/thread ----
    float wir[32], wiz[32], win_[32], whr[32], whz[32], whn[32], wo[32];
#pragma unroll
    for (int i = 0; i < 32; i++) {
        int k = k0 + i;
        wir[i]  = Wih[(size_t)(j        ) * 256 + k];
        wiz[i]  = Wih[(size_t)(j + 256  ) * 256 + k];
        win_[i] = Wih[(size_t)(j + 512  ) * 256 + k];
        whr[i]  = Whh[(size_t)(j        ) * 256 + k];
        whz[i]  = Whh[(size_t)(j + 256  ) * 256 + k];
        whn[i]  = Whh[(size_t)(j + 512  ) * 256 + k];
        wo[i]   = Wo [(size_t)j * 256 + k];
    }
    float br   = bih[j]       + bhh[j];
    float bz   = bih[j + 256] + bhh[j + 256];
    float bn_i = bih[j + 512];
    float bn_h = bhh[j + 512];
    float bO   = ob[j];

    sx[SPAD(t)] = latent[b * 256 + t];
    sh[SPAD(t)] = 0.f;
    float hprev = 0.f, ghr = 0.f, ghz = 0.f, ghn = 0.f;
    cluster_sync_();

    float* outb = out + (size_t)b * TOTAL;

    for (int n = 0; n < NCH; n++) {
        // -------- Phase A: gi partials + combine with precomputed gh --------
        float pr = ghr, pz = ghz, pn = 0.f, ph = ghn;
#pragma unroll
        for (int i4 = 0; i4 < 8; i4++) {
            float4 xv = *reinterpret_cast<const float4*>(sx + s * 36 + i4 * 4);
            FMA4(pr, wir, i4)
            FMA4(pz, wiz, i4)
            FMA4(pn, win_, i4)
        }
#pragma unroll
        for (int m = 4; m >= 1; m >>= 1) {
            pr += __shfl_xor_sync(0xffffffffu, pr, m);
            pz += __shfl_xor_sync(0xffffffffu, pz, m);
            pn += __shfl_xor_sync(0xffffffffu, pn, m);
            ph += __shfl_xor_sync(0xffffffffu, ph, m);
        }
        float rg   = 1.f / (1.f + __expf(-(pr + br)));
        float zg   = 1.f / (1.f + __expf(-(pz + bz)));
        float ng   = tanhf(pn + bn_i + rg * (ph + bn_h));
        float hnew = fmaf(zg, hprev - ng, ng);   // (1-z)*n + z*h
        hprev = hnew;
        st_remote(&sh[SPAD(j)], s, hnew);        // lane s -> rank s
        cluster_sync_();

        // -------- Phase B: gh_{t+1} partials + output chunk --------
        ghr = 0.f; ghz = 0.f; ghn = 0.f;
        float po = 0.f;
#pragma unroll
        for (int i4 = 0; i4 < 8; i4++) {
            float4 xv = *reinterpret_cast<const float4*>(sh + s * 36 + i4 * 4);
            FMA4(ghr, whr, i4)
            FMA4(ghz, whz, i4)
            FMA4(ghn, whn, i4)
            FMA4(po,  wo,  i4)
        }
#pragma unroll
        for (int m = 4; m >= 1; m >>= 1)
            po += __shfl_xor_sync(0xffffffffu, po, m);
        float c = po + bO;
        st_remote(&sx[SPAD(j)], s, c);           // chunk feeds back as next x
        if (s == 0) outb[(size_t)n * 256 + j] = c;
        cluster_sync_();
    }
}

// =====================================================================
// launch
// =====================================================================
extern "C" void kernel_launch(void* const* d_in, const int* in_sizes, int n_in,
                              void* d_out, int out_size)
{
    const float* genome  = (const float*)d_in[0];
    const float* embedW  = (const float*)d_in[1];
    const float* embedB  = (const float*)d_in[2];
    const float* qkvW    = (const float*)d_in[3];
    const float* qkvB    = (const float*)d_in[4];
    const float* projW   = (const float*)d_in[5];
    const float* projB   = (const float*)d_in[6];
    const float* ln1g    = (const float*)d_in[7];
    const float* ln1b    = (const float*)d_in[8];
    const float* ln2g    = (const float*)d_in[9];
    const float* ln2b    = (const float*)d_in[10];
    const float* W1      = (const float*)d_in[11];
    const float* B1      = (const float*)d_in[12];
    const float* W2      = (const float*)d_in[13];
    const float* B2      = (const float*)d_in[14];
    const float* gWih    = (const float*)d_in[15];
    const float* gWhh    = (const float*)d_in[16];
    const float* gbih    = (const float*)d_in[17];
    const float* gbhh    = (const float*)d_in[18];
    const float* oW      = (const float*)d_in[19];
    const float* oB      = (const float*)d_in[20];
    float* out = (float*)d_out;

    float *p_h, *p_qkv, *p_attn, *p_tmp, *p_ffn, *p_lat;
    cudaGetSymbolAddress((void**)&p_h,    g_h);
    cudaGetSymbolAddress((void**)&p_qkv,  g_qkv);
    cudaGetSymbolAddress((void**)&p_attn, g_attn);
    cudaGetSymbolAddress((void**)&p_tmp,  g_tmp);
    cudaGetSymbolAddress((void**)&p_ffn,  g_ffn);
    cudaGetSymbolAddress((void**)&p_lat,  g_latent);

    embed_kernel<<<BATCH * GL, Hdim>>>(genome, embedW, embedB, p_h);

    for (int l = 0; l < NLAY; l++) {
        gemm_rows4<3 * Hdim, Hdim, false><<<64, 3 * Hdim>>>(
            p_h, qkvW + (size_t)l * 3 * Hdim * Hdim, qkvB + l * 3 * Hdim, p_qkv);
        attn_kernel<<<BATCH * NH, 256>>>(p_qkv, p_attn);
        gemm_rows4<Hdim, Hdim, false><<<64, Hdim>>>(
            p_attn, projW + (size_t)l * Hdim * Hdim, projB + l * Hdim, p_tmp);
        addln_kernel<<<BATCH * GL, Hdim>>>(p_tmp, p_h, ln1g + l * Hdim, ln1b + l * Hdim);
        gemm_rows4<4 * Hdim, Hdim, true><<<64, 4 * Hdim>>>(
            p_h, W1 + (size_t)l * 4 * Hdim * Hdim, B1 + l * 4 * Hdim, p_ffn);
        gemm_rows4<Hdim, 4 * Hdim, false><<<64, Hdim>>>(
            p_ffn, W2 + (size_t)l * 4 * Hdim * Hdim, B2 + l * Hdim, p_tmp);
        addln_kernel<<<BATCH * GL, Hdim>>>(p_tmp, p_h, ln2g + l * Hdim, ln2b + l * Hdim);
    }

    latent_kernel<<<BATCH, Hdim>>>(p_h, p_lat);

    gru_kernel<<<BATCH * GRU_CLUSTER, 256>>>(gWih, gWhh, gbih, gbhh, oW, oB, p_lat, out);
}

// round 3
// speedup vs baseline: 1.6153x; 1.6153x over previous
#include <cuda_runtime.h>
#include <cstdint>
#include <cstdio>

// ---------------- problem constants ----------------
#define Hdim   256
#define GD     16
#define GL     16
#define NLAY   2
#define NH     4
#define DH     64
#define CS     256
#define TOTAL  263168
#define NCH    1028
#define BATCH  16

// ---------------- device scratch (no allocation allowed) ----------------
__device__ float g_h[BATCH * GL * Hdim];
__device__ float g_qkv[BATCH * GL * 3 * Hdim];
__device__ float g_attn[BATCH * GL * Hdim];
__device__ float g_tmp[BATCH * GL * Hdim];
__device__ float g_ffn[BATCH * GL * 4 * Hdim];
__device__ float g_latent[BATCH * Hdim];
__device__ float g_wf[768 * 256];      // fused Wih @ Wo
__device__ float g_gia[17 * 768];      // rows 0..15: gi0 per batch; row 16: bfused

// =====================================================================
// Transformer preamble (unchanged from passing version)
// =====================================================================

__global__ void embed_kernel(const float* __restrict__ g,
                             const float* __restrict__ W,
                             const float* __restrict__ bias,
                             float* __restrict__ h)
{
    int row = blockIdx.x;
    int j   = threadIdx.x;
    __shared__ float sg[GD];
    if (j < GD) sg[j] = g[row * GD + j];
    __syncthreads();
    float a = bias[j];
    const float* w = W + j * GD;
#pragma unroll
    for (int d = 0; d < GD; d++) a = fmaf(sg[d], w[d], a);
    h[row * Hdim + j] = a;
}

template<int NOUT, int KD, bool RELU>
__global__ void gemm_rows4(const float* __restrict__ X,
                           const float* __restrict__ W,
                           const float* __restrict__ bias,
                           float* __restrict__ Y)
{
    __shared__ float sx[4 * KD];
    int j  = threadIdx.x;
    int r0 = blockIdx.x * 4;
    for (int i = j; i < 4 * KD; i += NOUT) sx[i] = X[r0 * KD + i];
    __syncthreads();
    float bv = bias[j];
    float a0 = bv, a1 = bv, a2 = bv, a3 = bv;
    const float* w = W + (size_t)j * KD;
#pragma unroll 4
    for (int k = 0; k < KD; k += 4) {
        float4 wv = *reinterpret_cast<const float4*>(w + k);
        a0 = fmaf(sx[0*KD + k    ], wv.x, a0);
        a0 = fmaf(sx[0*KD + k + 1], wv.y, a0);
        a0 = fmaf(sx[0*KD + k + 2], wv.z, a0);
        a0 = fmaf(sx[0*KD + k + 3], wv.w, a0);
        a1 = fmaf(sx[1*KD + k    ], wv.x, a1);
        a1 = fmaf(sx[1*KD + k + 1], wv.y, a1);
        a1 = fmaf(sx[1*KD + k + 2], wv.z, a1);
        a1 = fmaf(sx[1*KD + k + 3], wv.w, a1);
        a2 = fmaf(sx[2*KD + k    ], wv.x, a2);
        a2 = fmaf(sx[2*KD + k + 1], wv.y, a2);
        a2 = fmaf(sx[2*KD + k + 2], wv.z, a2);
        a2 = fmaf(sx[2*KD + k + 3], wv.w, a2);
        a3 = fmaf(sx[3*KD + k    ], wv.x, a3);
        a3 = fmaf(sx[3*KD + k + 1], wv.y, a3);
        a3 = fmaf(sx[3*KD + k + 2], wv.z, a3);
        a3 = fmaf(sx[3*KD + k + 3], wv.w, a3);
    }
    if (RELU) {
        a0 = fmaxf(a0, 0.f); a1 = fmaxf(a1, 0.f);
        a2 = fmaxf(a2, 0.f); a3 = fmaxf(a3, 0.f);
    }
    Y[(size_t)(r0 + 0) * NOUT + j] = a0;
    Y[(size_t)(r0 + 1) * NOUT + j] = a1;
    Y[(size_t)(r0 + 2) * NOUT + j] = a2;
    Y[(size_t)(r0 + 3) * NOUT + j] = a3;
}

__global__ void attn_kernel(const float* __restrict__ qkv,
                            float* __restrict__ obuf)
{
    int b    = blockIdx.x >> 2;
    int head = blockIdx.x & 3;
    __shared__ float sq[GL][DH], sk[GL][DH], sv[GL][DH], sa[GL][GL];
    int tid = threadIdx.x;
    for (int i = tid; i < GL * DH; i += 256) {
        int s_ = i >> 6, d = i & 63;
        int base = (b * GL + s_) * (3 * Hdim) + head * DH + d;
        sq[s_][d] = qkv[base];
        sk[s_][d] = qkv[base + Hdim];
        sv[s_][d] = qkv[base + 2 * Hdim];
    }
    __syncthreads();
    int s_ = tid >> 4, t_ = tid & 15;
    float sc = 0.f;
#pragma unroll
    for (int d = 0; d < DH; d++) sc = fmaf(sq[s_][d], sk[t_][d], sc);
    sc *= 0.125f;
    float mx = sc;
#pragma unroll
    for (int m = 8; m > 0; m >>= 1) mx = fmaxf(mx, __shfl_xor_sync(0xffffffffu, mx, m));
    float e = __expf(sc - mx);
    float sum = e;
#pragma unroll
    for (int m = 8; m > 0; m >>= 1) sum += __shfl_xor_sync(0xffffffffu, sum, m);
    sa[s_][t_] = e / sum;
    __syncthreads();
    int d4 = tid & 15; s_ = tid >> 4;
#pragma unroll
    for (int dd = 0; dd < 4; dd++) {
        int d = d4 * 4 + dd;
        float acc = 0.f;
#pragma unroll
        for (int t = 0; t < GL; t++) acc = fmaf(sa[s_][t], sv[t][d], acc);
        obuf[(b * GL + s_) * Hdim + head * DH + d] = acc;
    }
}

__global__ void addln_kernel(const float* __restrict__ y,
                             float* __restrict__ h,
                             const float* __restrict__ gamma,
                             const float* __restrict__ beta)
{
    int row = blockIdx.x;
    int j   = threadIdx.x;
    __shared__ float red[16];
    float v = y[row * Hdim + j] + h[row * Hdim + j];
    float s1 = v, s2 = v * v;
#pragma unroll
    for (int m = 16; m > 0; m >>= 1) {
        s1 += __shfl_xor_sync(0xffffffffu, s1, m);
        s2 += __shfl_xor_sync(0xffffffffu, s2, m);
    }
    int w = j >> 5;
    if ((j & 31) == 0) { red[w] = s1; red[8 + w] = s2; }
    __syncthreads();
    float S1 = 0.f, S2 = 0.f;
#pragma unroll
    for (int i = 0; i < 8; i++) { S1 += red[i]; S2 += red[8 + i]; }
    float mean = S1 * (1.f / 256.f);
    float var  = S2 * (1.f / 256.f) - mean * mean;
    h[row * Hdim + j] = (v - mean) * rsqrtf(var + 1e-5f) * gamma[j] + beta[j];
}

__global__ void latent_kernel(const float* __restrict__ h,
                              float* __restrict__ lat)
{
    int b = blockIdx.x, j = threadIdx.x;
    float a = 0.f;
#pragma unroll
    for (int s = 0; s < GL; s++) a += h[(b * GL + s) * Hdim + j];
    lat[b * Hdim + j] = a * (1.f / 16.f);
}

// =====================================================================
// Fusion precompute: Wf = Wih @ Wo   ([768,256] @ [256,256])
//   Wf[row][j] = sum_k Wih[row][k] * Wo[k][j]
// =====================================================================
__global__ void fuse_kernel(const float* __restrict__ Wih,
                            const float* __restrict__ Wo,
                            float* __restrict__ Wf)
{
    __shared__ float sw[4 * 256];
    int j  = threadIdx.x;          // 256
    int r0 = blockIdx.x * 4;       // 192 blocks
    for (int i = j; i < 1024; i += 256) sw[i] = Wih[(size_t)r0 * 256 + i];
    __syncthreads();
    float a0 = 0.f, a1 = 0.f, a2 = 0.f, a3 = 0.f;
#pragma unroll 4
    for (int k = 0; k < 256; k++) {
        float w = Wo[k * 256 + j];
        a0 = fmaf(sw[k      ], w, a0);
        a1 = fmaf(sw[256 + k], w, a1);
        a2 = fmaf(sw[512 + k], w, a2);
        a3 = fmaf(sw[768 + k], w, a3);
    }
    Wf[(size_t)(r0 + 0) * 256 + j] = a0;
    Wf[(size_t)(r0 + 1) * 256 + j] = a1;
    Wf[(size_t)(r0 + 2) * 256 + j] = a2;
    Wf[(size_t)(r0 + 3) * 256 + j] = a3;
}

// gia[v][row] = bih[row] + Wih[row]·x_v  where x_v = latent[v] (v<16) or ob (v==16)
__global__ void gia_kernel(const float* __restrict__ Wih,
                           const float* __restrict__ bih,
                           const float* __restrict__ latent,
                           const float* __restrict__ ob,
                           float* __restrict__ gia)
{
    int row  = blockIdx.x;          // 768
    int lane = threadIdx.x;         // 32
    float w[8];
#pragma unroll
    for (int i = 0; i < 8; i++) w[i] = Wih[(size_t)row * 256 + lane * 8 + i];
    float bi = bih[row];
    for (int v = 0; v < 17; v++) {
        const float* x = (v < 16) ? (latent + v * 256) : ob;
        float a = 0.f;
#pragma unroll
        for (int i = 0; i < 8; i++) a = fmaf(w[i], x[lane * 8 + i], a);
#pragma unroll
        for (int m = 16; m > 0; m >>= 1) a += __shfl_xor_sync(0xffffffffu, a, m);
        if (lane == 0) gia[v * 768 + row] = a + bi;
    }
}

// =====================================================================
// GRU scan: 16 clusters x 8 CTAs; fused gi (no chunk feedback through smem),
// merged r/z matrices, packed f32x2 FMAs, ONE cluster sync per step.
// =====================================================================

#define GRU_CLUSTER 8
__device__ __forceinline__ int SPAD(int i) { return i + ((i >> 5) << 2); }

__device__ __forceinline__ void st_remote(float* p, int rank, float v)
{
    uint32_t a = (uint32_t)__cvta_generic_to_shared(p);
    uint32_t ra;
    asm volatile("mapa.shared::cluster.u32 %0, %1, %2;" : "=r"(ra) : "r"(a), "r"(rank));
    asm volatile("st.shared::cluster.f32 [%0], %1;" :: "r"(ra), "f"(v) : "memory");
}

__device__ __forceinline__ unsigned long long pack2(float lo, float hi)
{
    unsigned long long u;
    asm("mov.b64 %0, {%1,%2};" : "=l"(u) : "f"(lo), "f"(hi));
    return u;
}
__device__ __forceinline__ float upadd(unsigned long long a)
{
    float lo, hi;
    asm("mov.b64 {%0,%1}, %2;" : "=f"(lo), "=f"(hi) : "l"(a));
    return lo + hi;
}
#define FMA2(acc, x, w) \
    asm("fma.rn.f32x2 %0, %1, %2, %0;" : "+l"(acc) : "l"(x), "l"(w))

__device__ __forceinline__ float sigf(float x)
{
    return __fdividef(1.f, 1.f + __expf(-x));
}
__device__ __forceinline__ float tanhfast(float x)
{
    float e = __expf(-2.f * fabsf(x));
    float t = __fdividef(1.f - e, 1.f + e);
    return copysignf(t, x);
}

__global__ void __cluster_dims__(GRU_CLUSTER, 1, 1) __launch_bounds__(256, 1)
gru_kernel(const float* __restrict__ Wf,  const float* __restrict__ Whh,
           const float* __restrict__ bhh, const float* __restrict__ gia,
           const float* __restrict__ Wo,  const float* __restrict__ ob,
           float* __restrict__ out)
{
    __shared__ __align__(16) float sh[2][296];

    unsigned r;
    asm("mov.u32 %0, %%cluster_ctarank;" : "=r"(r));
    int b  = blockIdx.x >> 3;
    int t  = threadIdx.x;
    int G  = t >> 3;
    int s  = t & 7;
    int j  = (int)r * 32 + G;
    int k0 = s * 32;

    // ---- packed register-resident weights: 5 x 16 u64 = 160 f32 ----
    unsigned long long wr[16], wz[16], wni[16], wnh[16], wo2[16];
#pragma unroll
    for (int i = 0; i < 16; i++) {
        int k = k0 + 2 * i;
        size_t rR = (size_t)j * 256 + k;
        size_t rZ = (size_t)(j + 256) * 256 + k;
        size_t rN = (size_t)(j + 512) * 256 + k;
        wr[i]  = pack2(Wf[rR] + Whh[rR], Wf[rR + 1] + Whh[rR + 1]);
        wz[i]  = pack2(Wf[rZ] + Whh[rZ], Wf[rZ + 1] + Whh[rZ + 1]);
        wni[i] = pack2(Wf[rN],           Wf[rN + 1]);
        wnh[i] = pack2(Whh[rN],          Whh[rN + 1]);
        wo2[i] = pack2(Wo[rR],           Wo[rR + 1]);
    }
    float br  = gia[16 * 768 + j]       + bhh[j];
    float bz  = gia[16 * 768 + 256 + j] + bhh[256 + j];
    float bni = gia[16 * 768 + 512 + j];
    float bnh = bhh[512 + j];
    float bO  = ob[j];

    // ---- peel step 0: x = latent, h_{-1} = 0 (gh = bhh) ----
    {
        float r0 = sigf(gia[b * 768 + j] + bhh[j]);
        float z0 = sigf(gia[b * 768 + 256 + j] + bhh[256 + j]);
        float n0 = tanhfast(gia[b * 768 + 512 + j] + r0 * bhh[512 + j]);
        float h0 = (1.f - z0) * n0;
        st_remote(&sh[0][SPAD(j)], s, h0);
        // hprev carried below
        asm volatile("barrier.cluster.arrive.aligned;" ::: "memory");
        asm volatile("barrier.cluster.wait.aligned;"   ::: "memory");
        // store h0 into hprev via register (re-declared below)
    }
    float r0g = sigf(gia[b * 768 + j] + bhh[j]);
    float z0g = sigf(gia[b * 768 + 256 + j] + bhh[256 + j]);
    float hprev = (1.f - z0g) * tanhfast(gia[b * 768 + 512 + j] + r0g * bhh[512 + j]);

    float* outb = out + (size_t)b * TOTAL;
    int p = 0;

    for (int n = 1; n < NCH; n++) {
        const float* cur = sh[p];
        unsigned long long ar = 0ull, az = 0ull, ani = 0ull, anh = 0ull, ao = 0ull;
#pragma unroll
        for (int i4 = 0; i4 < 8; i4++) {
            ulonglong2 uv = *reinterpret_cast<const ulonglong2*>(cur + s * 36 + i4 * 4);
            FMA2(ar,  uv.x, wr[2 * i4]);     FMA2(ar,  uv.y, wr[2 * i4 + 1]);
            FMA2(az,  uv.x, wz[2 * i4]);     FMA2(az,  uv.y, wz[2 * i4 + 1]);
            FMA2(ani, uv.x, wni[2 * i4]);    FMA2(ani, uv.y, wni[2 * i4 + 1]);
            FMA2(anh, uv.x, wnh[2 * i4]);    FMA2(anh, uv.y, wnh[2 * i4 + 1]);
            FMA2(ao,  uv.x, wo2[2 * i4]);    FMA2(ao,  uv.y, wo2[2 * i4 + 1]);
        }
        float vr  = upadd(ar);
        float vz  = upadd(az);
        float vni = upadd(ani);
        float vnh = upadd(anh);
        float vo  = upadd(ao);
#pragma unroll
        for (int m = 4; m >= 1; m >>= 1) {
            vr  += __shfl_xor_sync(0xffffffffu, vr,  m);
            vz  += __shfl_xor_sync(0xffffffffu, vz,  m);
            vni += __shfl_xor_sync(0xffffffffu, vni, m);
            vnh += __shfl_xor_sync(0xffffffffu, vnh, m);
            vo  += __shfl_xor_sync(0xffffffffu, vo,  m);
        }
        float rg   = sigf(vr + br);
        float zg   = sigf(vz + bz);
        float ng   = tanhfast(vni + bni + rg * (vnh + bnh));
        float hnew = fmaf(zg, hprev - ng, ng);
        hprev = hnew;
        st_remote(&sh[p ^ 1][SPAD(j)], s, hnew);
        asm volatile("barrier.cluster.arrive.aligned;" ::: "memory");
        if (s == 0) outb[(size_t)(n - 1) * 256 + j] = vo + bO;   // chunk_{n-1}
        asm volatile("barrier.cluster.wait.aligned;"   ::: "memory");
        p ^= 1;
    }

    // ---- epilogue: chunk_1027 = Wo · h_1027 ----
    {
        const float* cur = sh[p];
        unsigned long long ao = 0ull;
#pragma unroll
        for (int i4 = 0; i4 < 8; i4++) {
            ulonglong2 uv = *reinterpret_cast<const ulonglong2*>(cur + s * 36 + i4 * 4);
            FMA2(ao, uv.x, wo2[2 * i4]);
            FMA2(ao, uv.y, wo2[2 * i4 + 1]);
        }
        float vo = upadd(ao);
#pragma unroll
        for (int m = 4; m >= 1; m >>= 1)
            vo += __shfl_xor_sync(0xffffffffu, vo, m);
        if (s == 0) outb[(size_t)1027 * 256 + j] = vo + bO;
    }
}

// =====================================================================
// launch
// =====================================================================
extern "C" void kernel_launch(void* const* d_in, const int* in_sizes, int n_in,
                              void* d_out, int out_size)
{
    const float* genome  = (const float*)d_in[0];
    const float* embedW  = (const float*)d_in[1];
    const float* embedB  = (const float*)d_in[2];
    const float* qkvW    = (const float*)d_in[3];
    const float* qkvB    = (const float*)d_in[4];
    const float* projW   = (const float*)d_in[5];
    const float* projB   = (const float*)d_in[6];
    const float* ln1g    = (const float*)d_in[7];
    const float* ln1b    = (const float*)d_in[8];
    const float* ln2g    = (const float*)d_in[9];
    const float* ln2b    = (const float*)d_in[10];
    const float* W1      = (const float*)d_in[11];
    const float* B1      = (const float*)d_in[12];
    const float* W2      = (const float*)d_in[13];
    const float* B2      = (const float*)d_in[14];
    const float* gWih    = (const float*)d_in[15];
    const float* gWhh    = (const float*)d_in[16];
    const float* gbih    = (const float*)d_in[17];
    const float* gbhh    = (const float*)d_in[18];
    const float* oW      = (const float*)d_in[19];
    const float* oB      = (const float*)d_in[20];
    float* out = (float*)d_out;

    float *p_h, *p_qkv, *p_attn, *p_tmp, *p_ffn, *p_lat, *p_wf, *p_gia;
    cudaGetSymbolAddress((void**)&p_h,    g_h);
    cudaGetSymbolAddress((void**)&p_qkv,  g_qkv);
    cudaGetSymbolAddress((void**)&p_attn, g_attn);
    cudaGetSymbolAddress((void**)&p_tmp,  g_tmp);
    cudaGetSymbolAddress((void**)&p_ffn,  g_ffn);
    cudaGetSymbolAddress((void**)&p_lat,  g_latent);
    cudaGetSymbolAddress((void**)&p_wf,   g_wf);
    cudaGetSymbolAddress((void**)&p_gia,  g_gia);

    // independent of the transformer: fused Wih@Wo
    fuse_kernel<<<192, 256>>>(gWih, oW, p_wf);

    embed_kernel<<<BATCH * GL, Hdim>>>(genome, embedW, embedB, p_h);

    for (int l = 0; l < NLAY; l++) {
        gemm_rows4<3 * Hdim, Hdim, false><<<64, 3 * Hdim>>>(
            p_h, qkvW + (size_t)l * 3 * Hdim * Hdim, qkvB + l * 3 * Hdim, p_qkv);
        attn_kernel<<<BATCH * NH, 256>>>(p_qkv, p_attn);
        gemm_rows4<Hdim, Hdim, false><<<64, Hdim>>>(
            p_attn, projW + (size_t)l * Hdim * Hdim, projB + l * Hdim, p_tmp);
        addln_kernel<<<BATCH * GL, Hdim>>>(p_tmp, p_h, ln1g + l * Hdim, ln1b + l * Hdim);
        gemm_rows4<4 * Hdim, Hdim, true><<<64, 4 * Hdim>>>(
            p_h, W1 + (size_t)l * 4 * Hdim * Hdim, B1 + l * 4 * Hdim, p_ffn);
        gemm_rows4<Hdim, 4 * Hdim, false><<<64, Hdim>>>(
            p_ffn, W2 + (size_t)l * 4 * Hdim * Hdim, B2 + l * Hdim, p_tmp);
        addln_kernel<<<BATCH * GL, Hdim>>>(p_tmp, p_h, ln2g + l * Hdim, ln2b + l * Hdim);
    }

    latent_kernel<<<BATCH, Hdim>>>(p_h, p_lat);
    gia_kernel<<<768, 32>>>(gWih, gbih, p_lat, oB, p_gia);

    gru_kernel<<<BATCH * GRU_CLUSTER, 256>>>(p_wf, gWhh, gbhh, p_gia, oW, oB, out);
}

// round 5
// speedup vs baseline: 2.0914x; 1.2947x over previous
#include <cuda_runtime.h>
#include <cstdint>
#include <cstdio>

// ---------------- problem constants ----------------
#define Hdim   256
#define GD     16
#define GL     16
#define NLAY   2
#define NH     4
#define DH     64
#define CS     256
#define TOTAL  263168
#define NCH    1028
#define BATCH  16

// ---------------- device scratch (no allocation allowed) ----------------
__device__ float g_h[BATCH * GL * Hdim];
__device__ float g_qkv[BATCH * GL * 3 * Hdim];
__device__ float g_attn[BATCH * GL * Hdim];
__device__ float g_tmp[BATCH * GL * Hdim];
__device__ float g_ffn[BATCH * GL * 4 * Hdim];
__device__ float g_latent[BATCH * Hdim];
__device__ float g_wf[768 * 256];      // fused Wih @ Wo
__device__ float g_gia[17 * 768];      // rows 0..15: gi0 per batch; row 16: Wih·ob + bih

// =====================================================================
// Transformer preamble (unchanged)
// =====================================================================

__global__ void embed_kernel(const float* __restrict__ g,
                             const float* __restrict__ W,
                             const float* __restrict__ bias,
                             float* __restrict__ h)
{
    int row = blockIdx.x;
    int j   = threadIdx.x;
    __shared__ float sg[GD];
    if (j < GD) sg[j] = g[row * GD + j];
    __syncthreads();
    float a = bias[j];
    const float* w = W + j * GD;
#pragma unroll
    for (int d = 0; d < GD; d++) a = fmaf(sg[d], w[d], a);
    h[row * Hdim + j] = a;
}

template<int NOUT, int KD, bool RELU>
__global__ void gemm_rows4(const float* __restrict__ X,
                           const float* __restrict__ W,
                           const float* __restrict__ bias,
                           float* __restrict__ Y)
{
    __shared__ float sx[4 * KD];
    int j  = threadIdx.x;
    int r0 = blockIdx.x * 4;
    for (int i = j; i < 4 * KD; i += NOUT) sx[i] = X[r0 * KD + i];
    __syncthreads();
    float bv = bias[j];
    float a0 = bv, a1 = bv, a2 = bv, a3 = bv;
    const float* w = W + (size_t)j * KD;
#pragma unroll 4
    for (int k = 0; k < KD; k += 4) {
        float4 wv = *reinterpret_cast<const float4*>(w + k);
        a0 = fmaf(sx[0*KD + k    ], wv.x, a0);
        a0 = fmaf(sx[0*KD + k + 1], wv.y, a0);
        a0 = fmaf(sx[0*KD + k + 2], wv.z, a0);
        a0 = fmaf(sx[0*KD + k + 3], wv.w, a0);
        a1 = fmaf(sx[1*KD + k    ], wv.x, a1);
        a1 = fmaf(sx[1*KD + k + 1], wv.y, a1);
        a1 = fmaf(sx[1*KD + k + 2], wv.z, a1);
        a1 = fmaf(sx[1*KD + k + 3], wv.w, a1);
        a2 = fmaf(sx[2*KD + k    ], wv.x, a2);
        a2 = fmaf(sx[2*KD + k + 1], wv.y, a2);
        a2 = fmaf(sx[2*KD + k + 2], wv.z, a2);
        a2 = fmaf(sx[2*KD + k + 3], wv.w, a2);
        a3 = fmaf(sx[3*KD + k    ], wv.x, a3);
        a3 = fmaf(sx[3*KD + k + 1], wv.y, a3);
        a3 = fmaf(sx[3*KD + k + 2], wv.z, a3);
        a3 = fmaf(sx[3*KD + k + 3], wv.w, a3);
    }
    if (RELU) {
        a0 = fmaxf(a0, 0.f); a1 = fmaxf(a1, 0.f);
        a2 = fmaxf(a2, 0.f); a3 = fmaxf(a3, 0.f);
    }
    Y[(size_t)(r0 + 0) * NOUT + j] = a0;
    Y[(size_t)(r0 + 1) * NOUT + j] = a1;
    Y[(size_t)(r0 + 2) * NOUT + j] = a2;
    Y[(size_t)(r0 + 3) * NOUT + j] = a3;
}

__global__ void attn_kernel(const float* __restrict__ qkv,
                            float* __restrict__ obuf)
{
    int b    = blockIdx.x >> 2;
    int head = blockIdx.x & 3;
    __shared__ float sq[GL][DH], sk[GL][DH], sv[GL][DH], sa[GL][GL];
    int tid = threadIdx.x;
    for (int i = tid; i < GL * DH; i += 256) {
        int s_ = i >> 6, d = i & 63;
        int base = (b * GL + s_) * (3 * Hdim) + head * DH + d;
        sq[s_][d] = qkv[base];
        sk[s_][d] = qkv[base + Hdim];
        sv[s_][d] = qkv[base + 2 * Hdim];
    }
    __syncthreads();
    int s_ = tid >> 4, t_ = tid & 15;
    float sc = 0.f;
#pragma unroll
    for (int d = 0; d < DH; d++) sc = fmaf(sq[s_][d], sk[t_][d], sc);
    sc *= 0.125f;
    float mx = sc;
#pragma unroll
    for (int m = 8; m > 0; m >>= 1) mx = fmaxf(mx, __shfl_xor_sync(0xffffffffu, mx, m));
    float e = __expf(sc - mx);
    float sum = e;
#pragma unroll
    for (int m = 8; m > 0; m >>= 1) sum += __shfl_xor_sync(0xffffffffu, sum, m);
    sa[s_][t_] = e / sum;
    __syncthreads();
    int d4 = tid & 15; s_ = tid >> 4;
#pragma unroll
    for (int dd = 0; dd < 4; dd++) {
        int d = d4 * 4 + dd;
        float acc = 0.f;
#pragma unroll
        for (int t = 0; t < GL; t++) acc = fmaf(sa[s_][t], sv[t][d], acc);
        obuf[(b * GL + s_) * Hdim + head * DH + d] = acc;
    }
}

__global__ void addln_kernel(const float* __restrict__ y,
                             float* __restrict__ h,
                             const float* __restrict__ gamma,
                             const float* __restrict__ beta)
{
    int row = blockIdx.x;
    int j   = threadIdx.x;
    __shared__ float red[16];
    float v = y[row * Hdim + j] + h[row * Hdim + j];
    float s1 = v, s2 = v * v;
#pragma unroll
    for (int m = 16; m > 0; m >>= 1) {
        s1 += __shfl_xor_sync(0xffffffffu, s1, m);
        s2 += __shfl_xor_sync(0xffffffffu, s2, m);
    }
    int w = j >> 5;
    if ((j & 31) == 0) { red[w] = s1; red[8 + w] = s2; }
    __syncthreads();
    float S1 = 0.f, S2 = 0.f;
#pragma unroll
    for (int i = 0; i < 8; i++) { S1 += red[i]; S2 += red[8 + i]; }
    float mean = S1 * (1.f / 256.f);
    float var  = S2 * (1.f / 256.f) - mean * mean;
    h[row * Hdim + j] = (v - mean) * rsqrtf(var + 1e-5f) * gamma[j] + beta[j];
}

__global__ void latent_kernel(const float* __restrict__ h,
                              float* __restrict__ lat)
{
    int b = blockIdx.x, j = threadIdx.x;
    float a = 0.f;
#pragma unroll
    for (int s = 0; s < GL; s++) a += h[(b * GL + s) * Hdim + j];
    lat[b * Hdim + j] = a * (1.f / 16.f);
}

// =====================================================================
// Fusion precompute: Wf = Wih @ Wo
// =====================================================================
__global__ void fuse_kernel(const float* __restrict__ Wih,
                            const float* __restrict__ Wo,
                            float* __restrict__ Wf)
{
    __shared__ float sw[4 * 256];
    int j  = threadIdx.x;
    int r0 = blockIdx.x * 4;
    for (int i = j; i < 1024; i += 256) sw[i] = Wih[(size_t)r0 * 256 + i];
    __syncthreads();
    float a0 = 0.f, a1 = 0.f, a2 = 0.f, a3 = 0.f;
#pragma unroll 4
    for (int k = 0; k < 256; k++) {
        float w = Wo[k * 256 + j];
        a0 = fmaf(sw[k      ], w, a0);
        a1 = fmaf(sw[256 + k], w, a1);
        a2 = fmaf(sw[512 + k], w, a2);
        a3 = fmaf(sw[768 + k], w, a3);
    }
    Wf[(size_t)(r0 + 0) * 256 + j] = a0;
    Wf[(size_t)(r0 + 1) * 256 + j] = a1;
    Wf[(size_t)(r0 + 2) * 256 + j] = a2;
    Wf[(size_t)(r0 + 3) * 256 + j] = a3;
}

__global__ void gia_kernel(const float* __restrict__ Wih,
                           const float* __restrict__ bih,
                           const float* __restrict__ latent,
                           const float* __restrict__ ob,
                           float* __restrict__ gia)
{
    int row  = blockIdx.x;
    int lane = threadIdx.x;
    float w[8];
#pragma unroll
    for (int i = 0; i < 8; i++) w[i] = Wih[(size_t)row * 256 + lane * 8 + i];
    float bi = bih[row];
    for (int v = 0; v < 17; v++) {
        const float* x = (v < 16) ? (latent + v * 256) : ob;
        float a = 0.f;
#pragma unroll
        for (int i = 0; i < 8; i++) a = fmaf(w[i], x[lane * 8 + i], a);
#pragma unroll
        for (int m = 16; m > 0; m >>= 1) a += __shfl_xor_sync(0xffffffffu, a, m);
        if (lane == 0) gia[v * 768 + row] = a + bi;
    }
}

// =====================================================================
// GRU scan: 16 clusters x 8 CTAs, mbarrier-tx pipeline (no cluster.sync/step)
// =====================================================================

#define GRU_CLUSTER 8

__device__ __forceinline__ uint32_t smem_u32(const void* p)
{
    return (uint32_t)__cvta_generic_to_shared(p);
}
__device__ __forceinline__ uint32_t mapa_u32(uint32_t a, int rank)
{
    uint32_t ra;
    asm volatile("mapa.shared::cluster.u32 %0, %1, %2;" : "=r"(ra) : "r"(a), "r"(rank));
    return ra;
}
__device__ __forceinline__ void cluster_sync_()
{
    asm volatile("barrier.cluster.arrive.aligned;" ::: "memory");
    asm volatile("barrier.cluster.wait.aligned;"   ::: "memory");
}
__device__ __forceinline__ void mbar_init(uint32_t mbar, uint32_t cnt)
{
    asm volatile("mbarrier.init.shared.b64 [%0], %1;" :: "r"(mbar), "r"(cnt) : "memory");
}
__device__ __forceinline__ void mbar_expect_tx(uint32_t mbar, uint32_t bytes)
{
    asm volatile("mbarrier.arrive.expect_tx.shared.b64 _, [%0], %1;"
                 :: "r"(mbar), "r"(bytes) : "memory");
}
__device__ __forceinline__ void mbar_wait(uint32_t mbar, uint32_t phase)
{
    asm volatile(
        "{\n\t"
        ".reg .pred P;\n\t"
        "WL_%=:\n\t"
        "mbarrier.try_wait.parity.acquire.cta.shared::cta.b64 P, [%0], %1, 0x989680;\n\t"
        "@!P bra WL_%=;\n\t"
        "}" :: "r"(mbar), "r"(phase) : "memory");
}
// 128B SMEM -> remote SMEM bulk copy, tx-completing the remote mbarrier
__device__ __forceinline__ void bulk128(uint32_t rdst, uint32_t lsrc, uint32_t rmbar)
{
    asm volatile(
        "cp.async.bulk.shared::cluster.shared::cta.mbarrier::complete_tx::bytes "
        "[%0], [%1], 128, [%2];"
        :: "r"(rdst), "r"(lsrc), "r"(rmbar) : "memory");
}
__device__ __forceinline__ void fence_proxy_async_cta()
{
    asm volatile("fence.proxy.async.shared::cta;" ::: "memory");
}

__device__ __forceinline__ unsigned long long pack2(float lo, float hi)
{
    unsigned long long u;
    asm("mov.b64 %0, {%1,%2};" : "=l"(u) : "f"(lo), "f"(hi));
    return u;
}
__device__ __forceinline__ float upadd(unsigned long long a)
{
    float lo, hi;
    asm("mov.b64 {%0,%1}, %2;" : "=f"(lo), "=f"(hi) : "l"(a));
    return lo + hi;
}
#define FMA2(acc, x, w) \
    asm("fma.rn.f32x2 %0, %1, %2, %0;" : "+l"(acc) : "l"(x), "l"(w))

__device__ __forceinline__ float sigf(float x)
{
    return __fdividef(1.f, 1.f + __expf(-x));
}
__device__ __forceinline__ float tanhfast(float x)
{
    float e = __expf(-2.f * fabsf(x));
    float t = __fdividef(1.f - e, 1.f + e);
    return copysignf(t, x);
}

__global__ void __cluster_dims__(GRU_CLUSTER, 1, 1) __launch_bounds__(256, 1)
gru_kernel(const float* __restrict__ Wf,  const float* __restrict__ Whh,
           const float* __restrict__ bhh, const float* __restrict__ gia,
           const float* __restrict__ Wo,  const float* __restrict__ ob,
           float* __restrict__ out)
{
    __shared__ __align__(16) float sh[2][296];     // h buffers (padded view: rank slice at r*36)
    __shared__ __align__(16) float stage[2][32];   // local 32-value staging
    __shared__ __align__(8)  unsigned long long mb[2];

    unsigned r;
    asm("mov.u32 %0, %%cluster_ctarank;" : "=r"(r));
    int b  = blockIdx.x >> 3;
    int t  = threadIdx.x;
    int G  = t >> 3;
    int s  = t & 7;
    int j  = (int)r * 32 + G;
    int k0 = s * 32;

    // local/remote addresses
    uint32_t mb_l0 = smem_u32(&mb[0]);
    uint32_t mb_l1 = smem_u32(&mb[1]);
    // bulk routing for t<8: this CTA's 32-value slice lands at byte offset r*144
    uint32_t rdst0 = 0, rdst1 = 0, rmb0 = 0, rmb1 = 0, lsrc0 = 0, lsrc1 = 0;
    if (t < 8) {
        uint32_t d0 = smem_u32(&sh[0][0]) + (uint32_t)r * 144u;
        uint32_t d1 = smem_u32(&sh[1][0]) + (uint32_t)r * 144u;
        rdst0 = mapa_u32(d0, t);
        rdst1 = mapa_u32(d1, t);
        rmb0  = mapa_u32(mb_l0, t);
        rmb1  = mapa_u32(mb_l1, t);
        lsrc0 = smem_u32(&stage[0][0]);
        lsrc1 = smem_u32(&stage[1][0]);
    }

    // ---- packed register-resident weights: 5 x 16 u64 = 160 f32 ----
    unsigned long long wr[16], wz[16], wni[16], wnh[16], wo2[16];
#pragma unroll
    for (int i = 0; i < 16; i++) {
        int k = k0 + 2 * i;
        size_t rR = (size_t)j * 256 + k;
        size_t rZ = (size_t)(j + 256) * 256 + k;
        size_t rN = (size_t)(j + 512) * 256 + k;
        wr[i]  = pack2(Wf[rR] + Whh[rR], Wf[rR + 1] + Whh[rR + 1]);
        wz[i]  = pack2(Wf[rZ] + Whh[rZ], Wf[rZ + 1] + Whh[rZ + 1]);
        wni[i] = pack2(Wf[rN],           Wf[rN + 1]);
        wnh[i] = pack2(Whh[rN],          Whh[rN + 1]);
        wo2[i] = pack2(Wo[rR],           Wo[rR + 1]);
    }
    float br  = gia[16 * 768 + j]       + bhh[j];
    float bz  = gia[16 * 768 + 256 + j] + bhh[256 + j];
    float bni = gia[16 * 768 + 512 + j];
    float bnh = bhh[512 + j];
    float bO  = ob[j];

    // ---- mbarrier init + arm both phases, then make visible cluster-wide ----
    if (t == 0) {
        mbar_init(mb_l0, 1);
        mbar_init(mb_l1, 1);
        mbar_expect_tx(mb_l0, 1024);
        mbar_expect_tx(mb_l1, 1024);
    }
    cluster_sync_();

    // ---- peel step 0: x = latent, h_{-1} = 0 ----
    float r0g = sigf(gia[b * 768 + j] + bhh[j]);
    float z0g = sigf(gia[b * 768 + 256 + j] + bhh[256 + j]);
    float hprev = (1.f - z0g) * tanhfast(gia[b * 768 + 512 + j] + r0g * bhh[512 + j]);
    if (s == 0) stage[0][G] = hprev;
    __syncthreads();
    if (t < 8) {
        fence_proxy_async_cta();
        bulk128(rdst0, lsrc0, rmb0);
    }

    float* outb = out + (size_t)b * TOTAL;
    int p = 0;
    int ph0 = 0, ph1 = 0;

    for (int n = 1; n < NCH; n++) {
        // wait for h_{n-1} in sh[p]
        if (p == 0) { mbar_wait(mb_l0, ph0); ph0 ^= 1; if (t == 0) mbar_expect_tx(mb_l0, 1024); }
        else        { mbar_wait(mb_l1, ph1); ph1 ^= 1; if (t == 0) mbar_expect_tx(mb_l1, 1024); }

        const float* cur = sh[p];
        unsigned long long ar = 0ull, az = 0ull, ani = 0ull, anh = 0ull, ao = 0ull;
#pragma unroll
        for (int i4 = 0; i4 < 8; i4++) {
            ulonglong2 uv = *reinterpret_cast<const ulonglong2*>(cur + s * 36 + i4 * 4);
            FMA2(ar,  uv.x, wr[2 * i4]);     FMA2(ar,  uv.y, wr[2 * i4 + 1]);
            FMA2(az,  uv.x, wz[2 * i4]);     FMA2(az,  uv.y, wz[2 * i4 + 1]);
            FMA2(ani, uv.x, wni[2 * i4]);    FMA2(ani, uv.y, wni[2 * i4 + 1]);
            FMA2(anh, uv.x, wnh[2 * i4]);    FMA2(anh, uv.y, wnh[2 * i4 + 1]);
            FMA2(ao,  uv.x, wo2[2 * i4]);    FMA2(ao,  uv.y, wo2[2 * i4 + 1]);
        }
        float vr  = upadd(ar);
        float vz  = upadd(az);
        float vni = upadd(ani);
        float vnh = upadd(anh);
        float vo  = upadd(ao);
#pragma unroll
        for (int m = 4; m >= 1; m >>= 1) {
            vr  += __shfl_xor_sync(0xffffffffu, vr,  m);
            vz  += __shfl_xor_sync(0xffffffffu, vz,  m);
            vni += __shfl_xor_sync(0xffffffffu, vni, m);
            vnh += __shfl_xor_sync(0xffffffffu, vnh, m);
            vo  += __shfl_xor_sync(0xffffffffu, vo,  m);
        }

        float rg   = sigf(vr + br);
        float zg   = sigf(vz + bz);
        float ng   = tanhfast(vni + bni + rg * (vnh + bnh));
        float hnew = fmaf(zg, hprev - ng, ng);
        hprev = hnew;

        int q = p ^ 1;                     // h_n goes into sh[q]
        if (s == 0) stage[q][G] = hnew;
        __syncthreads();
        if (t < 8) {
            fence_proxy_async_cta();
            if (q == 0) bulk128(rdst0, lsrc0, rmb0);
            else        bulk128(rdst1, lsrc1, rmb1);
        }
        if (s == 0) outb[(size_t)(n - 1) * 256 + j] = vo + bO;   // chunk_{n-1}
        p = q;
    }

    // ---- epilogue: chunk_1027 = Wo · h_1027 (h_1027 in sh[p]) ----
    if (p == 0) { mbar_wait(mb_l0, ph0); }
    else        { mbar_wait(mb_l1, ph1); }
    {
        const float* cur = sh[p];
        unsigned long long ao = 0ull;
#pragma unroll
        for (int i4 = 0; i4 < 8; i4++) {
            ulonglong2 uv = *reinterpret_cast<const ulonglong2*>(cur + s * 36 + i4 * 4);
            FMA2(ao, uv.x, wo2[2 * i4]);
            FMA2(ao, uv.y, wo2[2 * i4 + 1]);
        }
        float vo = upadd(ao);
#pragma unroll
        for (int m = 4; m >= 1; m >>= 1)
            vo += __shfl_xor_sync(0xffffffffu, vo, m);
        if (s == 0) outb[(size_t)1027 * 256 + j] = vo + bO;
    }
    cluster_sync_();   // keep SMEM alive until all in-flight bulks drain
}

// =====================================================================
// launch
// =====================================================================
extern "C" void kernel_launch(void* const* d_in, const int* in_sizes, int n_in,
                              void* d_out, int out_size)
{
    const float* genome  = (const float*)d_in[0];
    const float* embedW  = (const float*)d_in[1];
    const float* embedB  = (const float*)d_in[2];
    const float* qkvW    = (const float*)d_in[3];
    const float* qkvB    = (const float*)d_in[4];
    const float* projW   = (const float*)d_in[5];
    const float* projB   = (const float*)d_in[6];
    const float* ln1g    = (const float*)d_in[7];
    const float* ln1b    = (const float*)d_in[8];
    const float* ln2g    = (const float*)d_in[9];
    const float* ln2b    = (const float*)d_in[10];
    const float* W1      = (const float*)d_in[11];
    const float* B1      = (const float*)d_in[12];
    const float* W2      = (const float*)d_in[13];
    const float* B2      = (const float*)d_in[14];
    const float* gWih    = (const float*)d_in[15];
    const float* gWhh    = (const float*)d_in[16];
    const float* gbih    = (const float*)d_in[17];
    const float* gbhh    = (const float*)d_in[18];
    const float* oW      = (const float*)d_in[19];
    const float* oB      = (const float*)d_in[20];
    float* out = (float*)d_out;

    float *p_h, *p_qkv, *p_attn, *p_tmp, *p_ffn, *p_lat, *p_wf, *p_gia;
    cudaGetSymbolAddress((void**)&p_h,    g_h);
    cudaGetSymbolAddress((void**)&p_qkv,  g_qkv);
    cudaGetSymbolAddress((void**)&p_attn, g_attn);
    cudaGetSymbolAddress((void**)&p_tmp,  g_tmp);
    cudaGetSymbolAddress((void**)&p_ffn,  g_ffn);
    cudaGetSymbolAddress((void**)&p_lat,  g_latent);
    cudaGetSymbolAddress((void**)&p_wf,   g_wf);
    cudaGetSymbolAddress((void**)&p_gia,  g_gia);

    fuse_kernel<<<192, 256>>>(gWih, oW, p_wf);

    embed_kernel<<<BATCH * GL, Hdim>>>(genome, embedW, embedB, p_h);

    for (int l = 0; l < NLAY; l++) {
        gemm_rows4<3 * Hdim, Hdim, false><<<64, 3 * Hdim>>>(
            p_h, qkvW + (size_t)l * 3 * Hdim * Hdim, qkvB + l * 3 * Hdim, p_qkv);
        attn_kernel<<<BATCH * NH, 256>>>(p_qkv, p_attn);
        gemm_rows4<Hdim, Hdim, false><<<64, Hdim>>>(
            p_attn, projW + (size_t)l * Hdim * Hdim, projB + l * Hdim, p_tmp);
        addln_kernel<<<BATCH * GL, Hdim>>>(p_tmp, p_h, ln1g + l * Hdim, ln1b + l * Hdim);
        gemm_rows4<4 * Hdim, Hdim, true><<<64, 4 * Hdim>>>(
            p_h, W1 + (size_t)l * 4 * Hdim * Hdim, B1 + l * 4 * Hdim, p_ffn);
        gemm_rows4<Hdim, 4 * Hdim, false><<<64, Hdim>>>(
            p_ffn, W2 + (size_t)l * 4 * Hdim * Hdim, B2 + l * Hdim, p_tmp);
        addln_kernel<<<BATCH * GL, Hdim>>>(p_tmp, p_h, ln2g + l * Hdim, ln2b + l * Hdim);
    }

    latent_kernel<<<BATCH, Hdim>>>(p_h, p_lat);
    gia_kernel<<<768, 32>>>(gWih, gbih, p_lat, oB, p_gia);

    gru_kernel<<<BATCH * GRU_CLUSTER, 256>>>(p_wf, gWhh, gbhh, p_gia, oW, oB, out);
}

// round 7
// speedup vs baseline: 2.6404x; 1.2625x over previous
#include <cuda_runtime.h>
#include <cstdint>
#include <cstdio>

// ---------------- problem constants ----------------
#define Hdim   256
#define GD     16
#define GL     16
#define NLAY   2
#define NH     4
#define DH     64
#define CS     256
#define TOTAL  263168
#define NCH    1028
#define BATCH  16

// ---------------- device scratch (no allocation allowed) ----------------
__device__ float g_h[BATCH * GL * Hdim];
__device__ float g_qkv[BATCH * GL * 3 * Hdim];
__device__ float g_attn[BATCH * GL * Hdim];
__device__ float g_tmp[BATCH * GL * Hdim];
__device__ float g_ffn[BATCH * GL * 4 * Hdim];
__device__ float g_latent[BATCH * Hdim];
__device__ float g_wf[768 * 256];      // fused Wih @ Wo
__device__ float g_gia[17 * 768];      // rows 0..15: gi0 per batch; row 16: Wih·ob + bih

// =====================================================================
// Transformer preamble (unchanged)
// =====================================================================

__global__ void embed_kernel(const float* __restrict__ g,
                             const float* __restrict__ W,
                             const float* __restrict__ bias,
                             float* __restrict__ h)
{
    int row = blockIdx.x;
    int j   = threadIdx.x;
    __shared__ float sg[GD];
    if (j < GD) sg[j] = g[row * GD + j];
    __syncthreads();
    float a = bias[j];
    const float* w = W + j * GD;
#pragma unroll
    for (int d = 0; d < GD; d++) a = fmaf(sg[d], w[d], a);
    h[row * Hdim + j] = a;
}

template<int NOUT, int KD, bool RELU>
__global__ void gemm_rows4(const float* __restrict__ X,
                           const float* __restrict__ W,
                           const float* __restrict__ bias,
                           float* __restrict__ Y)
{
    __shared__ float sx[4 * KD];
    int j  = threadIdx.x;
    int r0 = blockIdx.x * 4;
    for (int i = j; i < 4 * KD; i += NOUT) sx[i] = X[r0 * KD + i];
    __syncthreads();
    float bv = bias[j];
    float a0 = bv, a1 = bv, a2 = bv, a3 = bv;
    const float* w = W + (size_t)j * KD;
#pragma unroll 4
    for (int k = 0; k < KD; k += 4) {
        float4 wv = *reinterpret_cast<const float4*>(w + k);
        a0 = fmaf(sx[0*KD + k    ], wv.x, a0);
        a0 = fmaf(sx[0*KD + k + 1], wv.y, a0);
        a0 = fmaf(sx[0*KD + k + 2], wv.z, a0);
        a0 = fmaf(sx[0*KD + k + 3], wv.w, a0);
        a1 = fmaf(sx[1*KD + k    ], wv.x, a1);
        a1 = fmaf(sx[1*KD + k + 1], wv.y, a1);
        a1 = fmaf(sx[1*KD + k + 2], wv.z, a1);
        a1 = fmaf(sx[1*KD + k + 3], wv.w, a1);
        a2 = fmaf(sx[2*KD + k    ], wv.x, a2);
        a2 = fmaf(sx[2*KD + k + 1], wv.y, a2);
        a2 = fmaf(sx[2*KD + k + 2], wv.z, a2);
        a2 = fmaf(sx[2*KD + k + 3], wv.w, a2);
        a3 = fmaf(sx[3*KD + k    ], wv.x, a3);
        a3 = fmaf(sx[3*KD + k + 1], wv.y, a3);
        a3 = fmaf(sx[3*KD + k + 2], wv.z, a3);
        a3 = fmaf(sx[3*KD + k + 3], wv.w, a3);
    }
    if (RELU) {
        a0 = fmaxf(a0, 0.f); a1 = fmaxf(a1, 0.f);
        a2 = fmaxf(a2, 0.f); a3 = fmaxf(a3, 0.f);
    }
    Y[(size_t)(r0 + 0) * NOUT + j] = a0;
    Y[(size_t)(r0 + 1) * NOUT + j] = a1;
    Y[(size_t)(r0 + 2) * NOUT + j] = a2;
    Y[(size_t)(r0 + 3) * NOUT + j] = a3;
}

__global__ void attn_kernel(const float* __restrict__ qkv,
                            float* __restrict__ obuf)
{
    int b    = blockIdx.x >> 2;
    int head = blockIdx.x & 3;
    __shared__ float sq[GL][DH], sk[GL][DH], sv[GL][DH], sa[GL][GL];
    int tid = threadIdx.x;
    for (int i = tid; i < GL * DH; i += 256) {
        int s_ = i >> 6, d = i & 63;
        int base = (b * GL + s_) * (3 * Hdim) + head * DH + d;
        sq[s_][d] = qkv[base];
        sk[s_][d] = qkv[base + Hdim];
        sv[s_][d] = qkv[base + 2 * Hdim];
    }
    __syncthreads();
    int s_ = tid >> 4, t_ = tid & 15;
    float sc = 0.f;
#pragma unroll
    for (int d = 0; d < DH; d++) sc = fmaf(sq[s_][d], sk[t_][d], sc);
    sc *= 0.125f;
    float mx = sc;
#pragma unroll
    for (int m = 8; m > 0; m >>= 1) mx = fmaxf(mx, __shfl_xor_sync(0xffffffffu, mx, m));
    float e = __expf(sc - mx);
    float sum = e;
#pragma unroll
    for (int m = 8; m > 0; m >>= 1) sum += __shfl_xor_sync(0xffffffffu, sum, m);
    sa[s_][t_] = e / sum;
    __syncthreads();
    int d4 = tid & 15; s_ = tid >> 4;
#pragma unroll
    for (int dd = 0; dd < 4; dd++) {
        int d = d4 * 4 + dd;
        float acc = 0.f;
#pragma unroll
        for (int t = 0; t < GL; t++) acc = fmaf(sa[s_][t], sv[t][d], acc);
        obuf[(b * GL + s_) * Hdim + head * DH + d] = acc;
    }
}

__global__ void addln_kernel(const float* __restrict__ y,
                             float* __restrict__ h,
                             const float* __restrict__ gamma,
                             const float* __restrict__ beta)
{
    int row = blockIdx.x;
    int j   = threadIdx.x;
    __shared__ float red[16];
    float v = y[row * Hdim + j] + h[row * Hdim + j];
    float s1 = v, s2 = v * v;
#pragma unroll
    for (int m = 16; m > 0; m >>= 1) {
        s1 += __shfl_xor_sync(0xffffffffu, s1, m);
        s2 += __shfl_xor_sync(0xffffffffu, s2, m);
    }
    int w = j >> 5;
    if ((j & 31) == 0) { red[w] = s1; red[8 + w] = s2; }
    __syncthreads();
    float S1 = 0.f, S2 = 0.f;
#pragma unroll
    for (int i = 0; i < 8; i++) { S1 += red[i]; S2 += red[8 + i]; }
    float mean = S1 * (1.f / 256.f);
    float var  = S2 * (1.f / 256.f) - mean * mean;
    h[row * Hdim + j] = (v - mean) * rsqrtf(var + 1e-5f) * gamma[j] + beta[j];
}

__global__ void latent_kernel(const float* __restrict__ h,
                              float* __restrict__ lat)
{
    int b = blockIdx.x, j = threadIdx.x;
    float a = 0.f;
#pragma unroll
    for (int s = 0; s < GL; s++) a += h[(b * GL + s) * Hdim + j];
    lat[b * Hdim + j] = a * (1.f / 16.f);
}

// =====================================================================
// Fusion precompute: Wf = Wih @ Wo
// =====================================================================
__global__ void fuse_kernel(const float* __restrict__ Wih,
                            const float* __restrict__ Wo,
                            float* __restrict__ Wf)
{
    __shared__ float sw[4 * 256];
    int j  = threadIdx.x;
    int r0 = blockIdx.x * 4;
    for (int i = j; i < 1024; i += 256) sw[i] = Wih[(size_t)r0 * 256 + i];
    __syncthreads();
    float a0 = 0.f, a1 = 0.f, a2 = 0.f, a3 = 0.f;
#pragma unroll 4
    for (int k = 0; k < 256; k++) {
        float w = Wo[k * 256 + j];
        a0 = fmaf(sw[k      ], w, a0);
        a1 = fmaf(sw[256 + k], w, a1);
        a2 = fmaf(sw[512 + k], w, a2);
        a3 = fmaf(sw[768 + k], w, a3);
    }
    Wf[(size_t)(r0 + 0) * 256 + j] = a0;
    Wf[(size_t)(r0 + 1) * 256 + j] = a1;
    Wf[(size_t)(r0 + 2) * 256 + j] = a2;
    Wf[(size_t)(r0 + 3) * 256 + j] = a3;
}

__global__ void gia_kernel(const float* __restrict__ Wih,
                           const float* __restrict__ bih,
                           const float* __restrict__ latent,
                           const float* __restrict__ ob,
                           float* __restrict__ gia)
{
    int row  = blockIdx.x;
    int lane = threadIdx.x;
    float w[8];
#pragma unroll
    for (int i = 0; i < 8; i++) w[i] = Wih[(size_t)row * 256 + lane * 8 + i];
    float bi = bih[row];
    for (int v = 0; v < 17; v++) {
        const float* x = (v < 16) ? (latent + v * 256) : ob;
        float a = 0.f;
#pragma unroll
        for (int i = 0; i < 8; i++) a = fmaf(w[i], x[lane * 8 + i], a);
#pragma unroll
        for (int m = 16; m > 0; m >>= 1) a += __shfl_xor_sync(0xffffffffu, a, m);
        if (lane == 0) gia[v * 768 + row] = a + bi;
    }
}

// =====================================================================
// GRU scan: 16 clusters x 8 CTAs; per-thread st.async broadcast,
// zero intra-CTA synchronization in the main loop.
// =====================================================================

#define GRU_CLUSTER 8
__device__ __forceinline__ int SPAD(int i) { return i + ((i >> 5) << 2); }

__device__ __forceinline__ uint32_t smem_u32(const void* p)
{
    return (uint32_t)__cvta_generic_to_shared(p);
}
__device__ __forceinline__ uint32_t mapa_u32(uint32_t a, int rank)
{
    uint32_t ra;
    asm volatile("mapa.shared::cluster.u32 %0, %1, %2;" : "=r"(ra) : "r"(a), "r"(rank));
    return ra;
}
__device__ __forceinline__ void cluster_sync_()
{
    asm volatile("barrier.cluster.arrive.aligned;" ::: "memory");
    asm volatile("barrier.cluster.wait.aligned;"   ::: "memory");
}
__device__ __forceinline__ void mbar_init(uint32_t mbar, uint32_t cnt)
{
    asm volatile("mbarrier.init.shared.b64 [%0], %1;" :: "r"(mbar), "r"(cnt) : "memory");
}
__device__ __forceinline__ void mbar_expect_tx(uint32_t mbar, uint32_t bytes)
{
    asm volatile("mbarrier.arrive.expect_tx.shared.b64 _, [%0], %1;"
                 :: "r"(mbar), "r"(bytes) : "memory");
}
__device__ __forceinline__ void mbar_wait(uint32_t mbar, uint32_t phase)
{
    asm volatile(
        "{\n\t"
        ".reg .pred P;\n\t"
        "WL_%=:\n\t"
        "mbarrier.try_wait.parity.acquire.cta.shared::cta.b64 P, [%0], %1, 0x989680;\n\t"
        "@!P bra WL_%=;\n\t"
        "}" :: "r"(mbar), "r"(phase) : "memory");
}
// single-f32 async store to remote CTA SMEM, tx-completing the remote mbarrier
__device__ __forceinline__ void st_async_f32(uint32_t rdst, float v, uint32_t rmbar)
{
    asm volatile(
        "st.async.weak.shared::cluster.mbarrier::complete_tx::bytes.b32 [%0], %1, [%2];"
        :: "r"(rdst), "r"(__float_as_uint(v)), "r"(rmbar) : "memory");
}

__device__ __forceinline__ unsigned long long pack2(float lo, float hi)
{
    unsigned long long u;
    asm("mov.b64 %0, {%1,%2};" : "=l"(u) : "f"(lo), "f"(hi));
    return u;
}
__device__ __forceinline__ float upadd(unsigned long long a)
{
    float lo, hi;
    asm("mov.b64 {%0,%1}, %2;" : "=f"(lo), "=f"(hi) : "l"(a));
    return lo + hi;
}
#define FMA2(acc, x, w) \
    asm("fma.rn.f32x2 %0, %1, %2, %0;" : "+l"(acc) : "l"(x), "l"(w))

__device__ __forceinline__ float sigf(float x)
{
    return __fdividef(1.f, 1.f + __expf(-x));
}
__device__ __forceinline__ float tanhfast(float x)
{
    float e = __expf(-2.f * fabsf(x));
    float t = __fdividef(1.f - e, 1.f + e);
    return copysignf(t, x);
}

__global__ void __cluster_dims__(GRU_CLUSTER, 1, 1) __launch_bounds__(256, 1)
gru_kernel(const float* __restrict__ Wf,  const float* __restrict__ Whh,
           const float* __restrict__ bhh, const float* __restrict__ gia,
           const float* __restrict__ Wo,  const float* __restrict__ ob,
           float* __restrict__ out)
{
    __shared__ __align__(16) float sh[2][296];     // h buffers (rank slice at r*36)
    __shared__ __align__(8)  unsigned long long mb[2];

    unsigned r;
    asm("mov.u32 %0, %%cluster_ctarank;" : "=r"(r));
    int b  = blockIdx.x >> 3;
    int t  = threadIdx.x;
    int G  = t >> 3;
    int s  = t & 7;
    int j  = (int)r * 32 + G;
    int k0 = s * 32;

    uint32_t mb_l0 = smem_u32(&mb[0]);
    uint32_t mb_l1 = smem_u32(&mb[1]);
    // per-thread remote targets: this thread delivers h[j] to rank s
    uint32_t rmb0  = mapa_u32(mb_l0, s);
    uint32_t rmb1  = mapa_u32(mb_l1, s);
    uint32_t rdst0 = mapa_u32(smem_u32(&sh[0][SPAD(j)]), s);
    uint32_t rdst1 = mapa_u32(smem_u32(&sh[1][SPAD(j)]), s);

    // ---- packed register-resident weights: 5 x 16 u64 = 160 f32 ----
    unsigned long long wr[16], wz[16], wni[16], wnh[16], wo2[16];
#pragma unroll
    for (int i = 0; i < 16; i++) {
        int k = k0 + 2 * i;
        size_t rR = (size_t)j * 256 + k;
        size_t rZ = (size_t)(j + 256) * 256 + k;
        size_t rN = (size_t)(j + 512) * 256 + k;
        wr[i]  = pack2(Wf[rR] + Whh[rR], Wf[rR + 1] + Whh[rR + 1]);
        wz[i]  = pack2(Wf[rZ] + Whh[rZ], Wf[rZ + 1] + Whh[rZ + 1]);
        wni[i] = pack2(Wf[rN],           Wf[rN + 1]);
        wnh[i] = pack2(Whh[rN],          Whh[rN + 1]);
        wo2[i] = pack2(Wo[rR],           Wo[rR + 1]);
    }
    float br  = gia[16 * 768 + j]       + bhh[j];
    float bz  = gia[16 * 768 + 256 + j] + bhh[256 + j];
    float bni = gia[16 * 768 + 512 + j];
    float bnh = bhh[512 + j];
    float bO  = ob[j];

    // ---- mbarrier init (count = 256 arrives/phase), arm both phases ----
    if (t == 0) {
        mbar_init(mb_l0, 256);
        mbar_init(mb_l1, 256);
    }
    __syncthreads();
    mbar_expect_tx(mb_l0, 4);   // every thread: arrive + expect its 4 incoming bytes
    mbar_expect_tx(mb_l1, 4);
    cluster_sync_();            // all barriers armed cluster-wide before any st.async

    // ---- peel step 0: x = latent, h_{-1} = 0 ----
    float r0g = sigf(gia[b * 768 + j] + bhh[j]);
    float z0g = sigf(gia[b * 768 + 256 + j] + bhh[256 + j]);
    float hprev = (1.f - z0g) * tanhfast(gia[b * 768 + 512 + j] + r0g * bhh[512 + j]);
    st_async_f32(rdst0, hprev, rmb0);     // lane s -> rank s, buffer 0

    float* outb = out + (size_t)b * TOTAL;
    int p = 0;
    int ph0 = 0, ph1 = 0;

    for (int n = 1; n < NCH; n++) {
        // wait for h_{n-1} in sh[p]; immediately re-arm this barrier (additive)
        if (p == 0) { mbar_wait(mb_l0, ph0); ph0 ^= 1; mbar_expect_tx(mb_l0, 4); }
        else        { mbar_wait(mb_l1, ph1); ph1 ^= 1; mbar_expect_tx(mb_l1, 4); }

        const float* cur = sh[p];
        unsigned long long ar = 0ull, az = 0ull, ani = 0ull, anh = 0ull, ao = 0ull;
#pragma unroll
        for (int i4 = 0; i4 < 8; i4++) {
            ulonglong2 uv = *reinterpret_cast<const ulonglong2*>(cur + s * 36 + i4 * 4);
            FMA2(ar,  uv.x, wr[2 * i4]);     FMA2(ar,  uv.y, wr[2 * i4 + 1]);
            FMA2(az,  uv.x, wz[2 * i4]);     FMA2(az,  uv.y, wz[2 * i4 + 1]);
            FMA2(ani, uv.x, wni[2 * i4]);    FMA2(ani, uv.y, wni[2 * i4 + 1]);
            FMA2(anh, uv.x, wnh[2 * i4]);    FMA2(anh, uv.y, wnh[2 * i4 + 1]);
            FMA2(ao,  uv.x, wo2[2 * i4]);    FMA2(ao,  uv.y, wo2[2 * i4 + 1]);
        }
        // ---- gate reductions first: h broadcast is the critical path ----
        float vr  = upadd(ar);
        float vz  = upadd(az);
        float vni = upadd(ani);
        float vnh = upadd(anh);
#pragma unroll
        for (int m = 4; m >= 1; m >>= 1) {
            vr  += __shfl_xor_sync(0xffffffffu, vr,  m);
            vz  += __shfl_xor_sync(0xffffffffu, vz,  m);
            vni += __shfl_xor_sync(0xffffffffu, vni, m);
            vnh += __shfl_xor_sync(0xffffffffu, vnh, m);
        }
        float rg   = sigf(vr + br);
        float zg   = sigf(vz + bz);
        float ng   = tanhfast(vni + bni + rg * (vnh + bnh));
        float hnew = fmaf(zg, hprev - ng, ng);
        hprev = hnew;

        int q = p ^ 1;
        if (q == 0) st_async_f32(rdst0, hnew, rmb0);   // fire-and-forget broadcast
        else        st_async_f32(rdst1, hnew, rmb1);

        // ---- deferred output-chunk reduction (hidden under DSMEM delivery) ----
        float vo = upadd(ao);
#pragma unroll
        for (int m = 4; m >= 1; m >>= 1)
            vo += __shfl_xor_sync(0xffffffffu, vo, m);
        if (s == 0) outb[(size_t)(n - 1) * 256 + j] = vo + bO;   // chunk_{n-1}
        p = q;
    }

    // ---- epilogue: chunk_1027 = Wo · h_1027 (h_1027 in sh[p]) ----
    if (p == 0) { mbar_wait(mb_l0, ph0); }
    else        { mbar_wait(mb_l1, ph1); }
    {
        const float* cur = sh[p];
        unsigned long long ao = 0ull;
#pragma unroll
        for (int i4 = 0; i4 < 8; i4++) {
            ulonglong2 uv = *reinterpret_cast<const ulonglong2*>(cur + s * 36 + i4 * 4);
            FMA2(ao, uv.x, wo2[2 * i4]);
            FMA2(ao, uv.y, wo2[2 * i4 + 1]);
        }
        float vo = upadd(ao);
#pragma unroll
        for (int m = 4; m >= 1; m >>= 1)
            vo += __shfl_xor_sync(0xffffffffu, vo, m);
        if (s == 0) outb[(size_t)1027 * 256 + j] = vo + bO;
    }
    cluster_sync_();   // keep SMEM alive until all in-flight st.asyncs drain
}

// =====================================================================
// launch
// =====================================================================
extern "C" void kernel_launch(void* const* d_in, const int* in_sizes, int n_in,
                              void* d_out, int out_size)
{
    const float* genome  = (const float*)d_in[0];
    const float* embedW  = (const float*)d_in[1];
    const float* embedB  = (const float*)d_in[2];
    const float* qkvW    = (const float*)d_in[3];
    const float* qkvB    = (const float*)d_in[4];
    const float* projW   = (const float*)d_in[5];
    const float* projB   = (const float*)d_in[6];
    const float* ln1g    = (const float*)d_in[7];
    const float* ln1b    = (const float*)d_in[8];
    const float* ln2g    = (const float*)d_in[9];
    const float* ln2b    = (const float*)d_in[10];
    const float* W1      = (const float*)d_in[11];
    const float* B1      = (const float*)d_in[12];
    const float* W2      = (const float*)d_in[13];
    const float* B2      = (const float*)d_in[14];
    const float* gWih    = (const float*)d_in[15];
    const float* gWhh    = (const float*)d_in[16];
    const float* gbih    = (const float*)d_in[17];
    const float* gbhh    = (const float*)d_in[18];
    const float* oW      = (const float*)d_in[19];
    const float* oB      = (const float*)d_in[20];
    float* out = (float*)d_out;

    float *p_h, *p_qkv, *p_attn, *p_tmp, *p_ffn, *p_lat, *p_wf, *p_gia;
    cudaGetSymbolAddress((void**)&p_h,    g_h);
    cudaGetSymbolAddress((void**)&p_qkv,  g_qkv);
    cudaGetSymbolAddress((void**)&p_attn, g_attn);
    cudaGetSymbolAddress((void**)&p_tmp,  g_tmp);
    cudaGetSymbolAddress((void**)&p_ffn,  g_ffn);
    cudaGetSymbolAddress((void**)&p_lat,  g_latent);
    cudaGetSymbolAddress((void**)&p_wf,   g_wf);
    cudaGetSymbolAddress((void**)&p_gia,  g_gia);

    fuse_kernel<<<192, 256>>>(gWih, oW, p_wf);

    embed_kernel<<<BATCH * GL, Hdim>>>(genome, embedW, embedB, p_h);

    for (int l = 0; l < NLAY; l++) {
        gemm_rows4<3 * Hdim, Hdim, false><<<64, 3 * Hdim>>>(
            p_h, qkvW + (size_t)l * 3 * Hdim * Hdim, qkvB + l * 3 * Hdim, p_qkv);
        attn_kernel<<<BATCH * NH, 256>>>(p_qkv, p_attn);
        gemm_rows4<Hdim, Hdim, false><<<64, Hdim>>>(
            p_attn, projW + (size_t)l * Hdim * Hdim, projB + l * Hdim, p_tmp);
        addln_kernel<<<BATCH * GL, Hdim>>>(p_tmp, p_h, ln1g + l * Hdim, ln1b + l * Hdim);
        gemm_rows4<4 * Hdim, Hdim, true><<<64, 4 * Hdim>>>(
            p_h, W1 + (size_t)l * 4 * Hdim * Hdim, B1 + l * 4 * Hdim, p_ffn);
        gemm_rows4<Hdim, 4 * Hdim, false><<<64, Hdim>>>(
            p_ffn, W2 + (size_t)l * 4 * Hdim * Hdim, B2 + l * Hdim, p_tmp);
        addln_kernel<<<BATCH * GL, Hdim>>>(p_tmp, p_h, ln2g + l * Hdim, ln2b + l * Hdim);
    }

    latent_kernel<<<BATCH, Hdim>>>(p_h, p_lat);
    gia_kernel<<<768, 32>>>(gWih, gbih, p_lat, oB, p_gia);

    gru_kernel<<<BATCH * GRU_CLUSTER, 256>>>(p_wf, gWhh, gbhh, p_gia, oW, oB, out);
}